// round 7
// baseline (speedup 1.0000x reference)
#include <cuda_runtime.h>
#include <cstdint>

#define D_FEAT   128
#define DV       32            // float4 per row
#define NMAX     100352        // >= N_NODES, padded
#define EMAX     1600000

#define STH      512           // scan threads per block
#define SITEMS   8             // items per thread
#define STILE    (STH * SITEMS)  // 4096 per tile
#define MAXTILES 32            // 100K/4096 = 25; must stay <= 32 and <= #SMs

// ---- scratch: __device__ globals (no allocation allowed) ----
__device__ int                g_idx64;       // 1 if indices are int64
__device__ unsigned long long g_epack[EMAX]; // {norm_bits:32 | src:32}
__device__ int                g_deg_out[NMAX];
__device__ int                g_deg_in[NMAX];
__device__ float              g_rdeg[NMAX];
__device__ int                g_row_start[NMAX + 1];
__device__ int                g_cursor[NMAX];
__device__ int                g_tile_state[MAXTILES]; // bit31 = valid, low 30 = tile total

// ---------------------------------------------------------------------------
// Zero degree arrays + scan state; block 0 probes the index dtype.
// int64 little-endian with values < 2^31 -> every odd 32-bit word is 0.
__global__ void zero_detect_kernel(const unsigned int* __restrict__ raw,
                                   int n_words, int n_nodes) {
    int i = blockIdx.x * blockDim.x + threadIdx.x;
    if (i < n_nodes) { g_deg_out[i] = 0; g_deg_in[i] = 0; }
    if (i < MAXTILES) g_tile_state[i] = 0;
    if (blockIdx.x == 0) {
        __shared__ int any;
        if (threadIdx.x == 0) any = 0;
        __syncthreads();
        int acc = 0;
        for (int w = threadIdx.x; w < n_words / 2; w += blockDim.x)
            acc |= (raw[2 * w + 1] != 0u);
        if (acc) atomicOr(&any, 1);
        __syncthreads();
        if (threadIdx.x == 0) g_idx64 = (any == 0);
    }
}

__device__ __forceinline__ void load_edge(const void* src, const void* dst,
                                          int e, int is64, int& s, int& d) {
    if (is64) {
        s = (int)((const long long*)src)[e];
        d = (int)((const long long*)dst)[e];
    } else {
        s = ((const int*)src)[e];
        d = ((const int*)dst)[e];
    }
}

// Degree histograms straight from the input buffers (no index scratch copy).
__global__ void hist_kernel(const void* __restrict__ src,
                            const void* __restrict__ dst, int n_edges) {
    int e = blockIdx.x * blockDim.x + threadIdx.x;
    if (e >= n_edges) return;
    int s, d;
    load_edge(src, dst, e, g_idx64, s, d);
    atomicAdd(&g_deg_out[s], 1);
    atomicAdd(&g_deg_in[d], 1);
}

// ---- single-pass co-resident scan: deg_in -> row_start/cursor, + rdeg -----
// All tiles (<= 25 blocks) are guaranteed co-resident (148 SMs), so each
// block publishes its tile total and spin-reads ALL predecessors' totals in
// one warp-parallel shot. No ticket, no multi-phase chain.
__global__ __launch_bounds__(STH) void scan_kernel(int n_nodes, int n_edges) {
    __shared__ int sh_warp[STH / 32];
    __shared__ int sh_prefix;
    const int tile = blockIdx.x;
    const int t    = threadIdx.x;
    const int lane = t & 31;
    const int wid  = t >> 5;
    const int base = tile * STILE + t * SITEMS;

    // load + thread-local exclusive scan
    int v[SITEMS], loc[SITEMS];
    int sum = 0;
    #pragma unroll
    for (int k = 0; k < SITEMS; k++) {
        int idx = base + k;
        v[k] = (idx < n_nodes) ? g_deg_in[idx] : 0;
        loc[k] = sum;
        sum += v[k];
    }

    // warp inclusive scan of per-thread sums
    int ws = sum;
    #pragma unroll
    for (int off = 1; off < 32; off <<= 1) {
        int nb = __shfl_up_sync(0xffffffffu, ws, off);
        if (lane >= off) ws += nb;
    }
    if (lane == 31) sh_warp[wid] = ws;
    __syncthreads();

    // warp 0 scans the warp totals -> exclusive
    if (wid == 0) {
        const int NW = STH / 32;
        int orig = (lane < NW) ? sh_warp[lane] : 0;
        int wv = orig;
        #pragma unroll
        for (int off = 1; off < NW; off <<= 1) {
            int nb = __shfl_up_sync(0xffffffffu, wv, off);
            if (lane >= off) wv += nb;
        }
        if (lane < NW) sh_warp[lane] = wv - orig;   // exclusive warp prefix
    }
    __syncthreads();

    // publish this tile's total (single 32-bit word => atomic visibility)
    if (t == STH - 1) {
        int total = sh_warp[(STH / 32) - 1] + ws;   // excl last warp + incl last thread
        *((volatile int*)&g_tile_state[tile]) = 0x40000000 | total;
    }

    // warp-parallel lookback over all predecessor tiles
    if (wid == 0) {
        int p = 0;
        if (lane < tile) {
            int s;
            do { s = *((volatile int*)&g_tile_state[lane]); } while (!(s & 0x40000000));
            p = s & 0x3fffffff;
        }
        #pragma unroll
        for (int off = 16; off > 0; off >>= 1)
            p += __shfl_xor_sync(0xffffffffu, p, off);
        if (lane == 0) sh_prefix = p;
    }
    __syncthreads();

    // final outputs: CSR offsets, cursors, rdeg (scan3 fused)
    int gexcl = sh_prefix + sh_warp[wid] + (ws - sum);
    #pragma unroll
    for (int k = 0; k < SITEMS; k++) {
        int i = base + k;
        if (i < n_nodes) {
            int r = gexcl + loc[k];
            g_row_start[i] = r;
            g_cursor[i]    = r;
            int dg = g_deg_out[i];
            g_rdeg[i] = rsqrtf((float)(dg > 0 ? dg : 1));
        }
    }
    if (tile == 0 && t == 0) g_row_start[n_nodes] = n_edges;
}

// ---- bucket edges by dst; single 8B scatter of packed {norm, src} ---------
__global__ void bucket_kernel(const void* __restrict__ src,
                              const void* __restrict__ dst, int n_edges) {
    int e = blockIdx.x * blockDim.x + threadIdx.x;
    if (e >= n_edges) return;
    int s, d;
    load_edge(src, dst, e, g_idx64, s, d);
    float norm = g_rdeg[s] * g_rdeg[d];
    int pos = atomicAdd(&g_cursor[d], 1);
    g_epack[pos] = (unsigned long long)(unsigned)s
                 | ((unsigned long long)__float_as_uint(norm) << 32);
}

// ---- gather: one warp per dst node, register accumulation -----------------
__global__ __launch_bounds__(256) void gather_kernel(
    const float4* __restrict__ x, float4* __restrict__ out, int n_nodes)
{
    int warp = (blockIdx.x * blockDim.x + threadIdx.x) >> 5;
    int lane = threadIdx.x & 31;
    if (warp >= n_nodes) return;

    int beg = g_row_start[warp];
    int end = g_row_start[warp + 1];

    float4 acc = make_float4(0.f, 0.f, 0.f, 0.f);

    for (int e = beg; e < end; e += 32) {
        int m = min(32, end - e);
        unsigned long long pv = 0ull;
        if (lane < m) pv = g_epack[e + lane];       // one coalesced 8B load
        int   sv = (int)(unsigned)pv;
        float nv = __uint_as_float((unsigned)(pv >> 32));
        #pragma unroll 8
        for (int j = 0; j < m; j++) {
            int   sj = __shfl_sync(0xffffffffu, sv, j);
            float nj = __shfl_sync(0xffffffffu, nv, j);
            float4 v = x[(size_t)sj * DV + lane];
            acc.x += v.x * nj;
            acc.y += v.y * nj;
            acc.z += v.z * nj;
            acc.w += v.w * nj;
        }
    }
    out[(size_t)warp * DV + lane] = acc;    // every row written -> no memset
}

// ---------------------------------------------------------------------------
extern "C" void kernel_launch(void* const* d_in, const int* in_sizes, int n_in,
                              void* d_out, int out_size)
{
    const float* x   = (const float*)d_in[0];
    const void*  src = d_in[1];
    const void*  dst = d_in[2];
    float*       out = (float*)d_out;

    int n_nodes = in_sizes[0] / D_FEAT;
    int n_edges = in_sizes[1];
    int scan_tiles = (n_nodes + STILE - 1) / STILE;  // 25 for 100K (<= 32, co-resident)

    int probe_words = 2048 < n_edges ? 2048 : n_edges;

    zero_detect_kernel<<<(n_nodes + 255) / 256, 256>>>(
        (const unsigned int*)src, probe_words, n_nodes);

    hist_kernel<<<(n_edges + 255) / 256, 256>>>(src, dst, n_edges);

    scan_kernel<<<scan_tiles, STH>>>(n_nodes, n_edges);

    bucket_kernel<<<(n_edges + 255) / 256, 256>>>(src, dst, n_edges);

    long long total_threads = (long long)n_nodes * 32;
    gather_kernel<<<(int)((total_threads + 255) / 256), 256>>>(
        (const float4*)x, (float4*)out, n_nodes);

    (void)n_in; (void)out_size;
}

// round 8
// speedup vs baseline: 1.1081x; 1.1081x over previous
#include <cuda_runtime.h>
#include <cstdint>

#define D_FEAT   128
#define DV       32            // float4 per row
#define NMAX     100352        // >= N_NODES, padded
#define EMAX     1600000

#define STH      512           // scan threads per block
#define SITEMS   8             // items per thread
#define STILE    (STH * SITEMS)  // 4096 per tile
#define MAXTILES 32            // 100K/4096 = 25; must stay <= 32 and <= #SMs

// ---- scratch: __device__ globals (no allocation allowed) ----
__device__ int   g_idx64;          // 1 if indices are int64
__device__ int   g_rank[EMAX];     // edge rank within its dst bucket
__device__ int   g_esrc[EMAX];     // dst-bucketed src ids
__device__ int   g_deg_out[NMAX];
__device__ int   g_deg_in[NMAX];
__device__ float g_rdeg[NMAX];
__device__ int   g_row_start[NMAX + 1];
__device__ int   g_tile_state[MAXTILES]; // bit30 = valid, low 30 = tile total

// ---------------------------------------------------------------------------
// Zero degree arrays + scan state; block 0 probes the index dtype.
// int64 little-endian with values < 2^31 -> every odd 32-bit word is 0.
__global__ void zero_detect_kernel(const unsigned int* __restrict__ raw,
                                   int n_words, int n_nodes) {
    int i = blockIdx.x * blockDim.x + threadIdx.x;
    if (i < n_nodes) { g_deg_out[i] = 0; g_deg_in[i] = 0; }
    if (i < MAXTILES) g_tile_state[i] = 0;
    if (blockIdx.x == 0) {
        __shared__ int any;
        if (threadIdx.x == 0) any = 0;
        __syncthreads();
        int acc = 0;
        for (int w = threadIdx.x; w < n_words / 2; w += blockDim.x)
            acc |= (raw[2 * w + 1] != 0u);
        if (acc) atomicOr(&any, 1);
        __syncthreads();
        if (threadIdx.x == 0) g_idx64 = (any == 0);
    }
}

__device__ __forceinline__ void load_edge(const void* src, const void* dst,
                                          int e, int is64, int& s, int& d) {
    if (is64) {
        s = (int)((const long long*)src)[e];
        d = (int)((const long long*)dst)[e];
    } else {
        s = ((const int*)src)[e];
        d = ((const int*)dst)[e];
    }
}

// Degree histograms; the deg_in atomic's RETURN VALUE is this edge's rank
// within its dst bucket -> saved for the atomic-free bucket pass.
__global__ void hist_kernel(const void* __restrict__ src,
                            const void* __restrict__ dst, int n_edges) {
    int e = blockIdx.x * blockDim.x + threadIdx.x;
    if (e >= n_edges) return;
    int s, d;
    load_edge(src, dst, e, g_idx64, s, d);
    atomicAdd(&g_deg_out[s], 1);
    g_rank[e] = atomicAdd(&g_deg_in[d], 1);
}

// ---- single-pass co-resident scan: deg_in -> row_start, + rdeg ------------
// All tiles (<= 25 blocks) co-resident on 148 SMs: each block publishes its
// tile total, then warp-parallel spin-reads all predecessors. No ticket.
__global__ __launch_bounds__(STH) void scan_kernel(int n_nodes, int n_edges) {
    __shared__ int sh_warp[STH / 32];
    __shared__ int sh_prefix;
    const int tile = blockIdx.x;
    const int t    = threadIdx.x;
    const int lane = t & 31;
    const int wid  = t >> 5;
    const int base = tile * STILE + t * SITEMS;

    int v[SITEMS], loc[SITEMS];
    int sum = 0;
    #pragma unroll
    for (int k = 0; k < SITEMS; k++) {
        int idx = base + k;
        v[k] = (idx < n_nodes) ? g_deg_in[idx] : 0;
        loc[k] = sum;
        sum += v[k];
    }

    int ws = sum;
    #pragma unroll
    for (int off = 1; off < 32; off <<= 1) {
        int nb = __shfl_up_sync(0xffffffffu, ws, off);
        if (lane >= off) ws += nb;
    }
    if (lane == 31) sh_warp[wid] = ws;
    __syncthreads();

    if (wid == 0) {
        const int NW = STH / 32;
        int orig = (lane < NW) ? sh_warp[lane] : 0;
        int wv = orig;
        #pragma unroll
        for (int off = 1; off < NW; off <<= 1) {
            int nb = __shfl_up_sync(0xffffffffu, wv, off);
            if (lane >= off) wv += nb;
        }
        if (lane < NW) sh_warp[lane] = wv - orig;   // exclusive warp prefix
    }
    __syncthreads();

    if (t == STH - 1) {
        int total = sh_warp[(STH / 32) - 1] + ws;
        *((volatile int*)&g_tile_state[tile]) = 0x40000000 | total;
    }

    if (wid == 0) {
        int p = 0;
        if (lane < tile) {
            int s;
            do { s = *((volatile int*)&g_tile_state[lane]); } while (!(s & 0x40000000));
            p = s & 0x3fffffff;
        }
        #pragma unroll
        for (int off = 16; off > 0; off >>= 1)
            p += __shfl_xor_sync(0xffffffffu, p, off);
        if (lane == 0) sh_prefix = p;
    }
    __syncthreads();

    int gexcl = sh_prefix + sh_warp[wid] + (ws - sum);
    #pragma unroll
    for (int k = 0; k < SITEMS; k++) {
        int i = base + k;
        if (i < n_nodes) {
            g_row_start[i] = gexcl + loc[k];
            int dg = g_deg_out[i];
            g_rdeg[i] = rsqrtf((float)(dg > 0 ? dg : 1));
        }
    }
    if (tile == 0 && t == 0) g_row_start[n_nodes] = n_edges;
}

// ---- bucket: atomic-free, pos = row_start[dst] + rank ---------------------
__global__ void bucket_kernel(const void* __restrict__ src,
                              const void* __restrict__ dst, int n_edges) {
    int e = blockIdx.x * blockDim.x + threadIdx.x;
    if (e >= n_edges) return;
    int s, d;
    load_edge(src, dst, e, g_idx64, s, d);
    g_esrc[g_row_start[d] + g_rank[e]] = s;   // single 4B random scatter
}

// ---- gather: one warp per dst node, register accumulation -----------------
// norm = rdeg[s] * rdeg[dst]: rdeg[dst] uniform per node, rdeg[s] gathered
// in the coalesced lane-load phase.
__global__ __launch_bounds__(256) void gather_kernel(
    const float4* __restrict__ x, float4* __restrict__ out, int n_nodes)
{
    int warp = (blockIdx.x * blockDim.x + threadIdx.x) >> 5;
    int lane = threadIdx.x & 31;
    if (warp >= n_nodes) return;

    int beg = g_row_start[warp];
    int end = g_row_start[warp + 1];
    float rd = g_rdeg[warp];                    // uniform, L1-hit

    float4 acc = make_float4(0.f, 0.f, 0.f, 0.f);

    for (int e = beg; e < end; e += 32) {
        int m = min(32, end - e);
        int   sv = 0;
        float nv = 0.f;
        if (lane < m) {
            sv = g_esrc[e + lane];              // coalesced 4B
            nv = g_rdeg[sv] * rd;               // 1 random 4B gather per edge
        }
        #pragma unroll 8
        for (int j = 0; j < m; j++) {
            int   sj = __shfl_sync(0xffffffffu, sv, j);
            float nj = __shfl_sync(0xffffffffu, nv, j);
            float4 v = x[(size_t)sj * DV + lane];
            acc.x += v.x * nj;
            acc.y += v.y * nj;
            acc.z += v.z * nj;
            acc.w += v.w * nj;
        }
    }
    out[(size_t)warp * DV + lane] = acc;        // every row written -> no memset
}

// ---------------------------------------------------------------------------
extern "C" void kernel_launch(void* const* d_in, const int* in_sizes, int n_in,
                              void* d_out, int out_size)
{
    const float* x   = (const float*)d_in[0];
    const void*  src = d_in[1];
    const void*  dst = d_in[2];
    float*       out = (float*)d_out;

    int n_nodes = in_sizes[0] / D_FEAT;
    int n_edges = in_sizes[1];
    int scan_tiles = (n_nodes + STILE - 1) / STILE;  // 25 for 100K

    int probe_words = 2048 < n_edges ? 2048 : n_edges;

    zero_detect_kernel<<<(n_nodes + 255) / 256, 256>>>(
        (const unsigned int*)src, probe_words, n_nodes);

    hist_kernel<<<(n_edges + 255) / 256, 256>>>(src, dst, n_edges);

    scan_kernel<<<scan_tiles, STH>>>(n_nodes, n_edges);

    bucket_kernel<<<(n_edges + 255) / 256, 256>>>(src, dst, n_edges);

    long long total_threads = (long long)n_nodes * 32;
    gather_kernel<<<(int)((total_threads + 255) / 256), 256>>>(
        (const float4*)x, (float4*)out, n_nodes);

    (void)n_in; (void)out_size;
}